// round 10
// baseline (speedup 1.0000x reference)
#include <cuda_runtime.h>

// ComplexSuperposition: B=128, T=128, D=512
// One kernel, producer/consumer overlap with TIME-STAGGERED producers:
//   blocks [0,128): persistent reducers. CTA r processes items {r, 128+r, 256+r, 384+r},
//                   item i = (batch i>>2, chunk i&3). Round k covers batches 32k..32k+31,
//                   so ready flags fire in batch order every ~T_red/4.
//   blocks [128, 128+4096): outer-product stores; 32 per batch, wait on g_ready[b]==4.
// Flags self-reset (last consumer of each batch zeroes them) -> no prologue kernel,
// clean state for every graph replay.
// d_out: [output_r (128*512*512 f32)][output_i (...)]

#define BB 128
#define TT 128
#define DD 512
#define NRED 128
#define NOUT (BB * 32)

__device__ float g_outr[BB * DD];
__device__ float g_outi[BB * DD];
__device__ int   g_ready[BB];   // 0 -> 4 by producers
__device__ int   g_done[BB];    // 0 -> 32 by consumers; 32nd resets both

__global__ void __launch_bounds__(256) main_k(const float* __restrict__ re,
                                              const float* __restrict__ im,
                                              const float* __restrict__ w,
                                              float* __restrict__ out) {
    __shared__ __align__(16) char smem_raw[8192];
    int bid = blockIdx.x;
    int tid = threadIdx.x;

    if (bid < NRED) {
        // ───────── persistent reducer: 4 items, batch-staggered ─────────
        float4 (*sr)[32] = (float4(*)[32])(smem_raw);
        float4 (*si)[32] = (float4(*)[32])(smem_raw + 4096);

        int j  = tid & 31;        // float4 lane within 128-float chunk
        int tg = tid >> 5;        // T-split group (0..7), 16 t's each

        for (int round = 0; round < 4; ++round) {
            int item  = round * NRED + bid;
            int b     = item >> 2;
            int chunk = item & 3;

            size_t base4 = ((size_t)b * TT * DD + chunk * 128 + j * 4) >> 2;
            const float4* rp = (const float4*)re + base4;
            const float4* ip = (const float4*)im + base4;
            const float*  wp = w + b * TT;

            float4 ar = make_float4(0.f, 0.f, 0.f, 0.f);
            float4 ai = make_float4(0.f, 0.f, 0.f, 0.f);

            int t0 = tg * 16;
#pragma unroll 16
            for (int k = 0; k < 16; ++k) {
                int t = t0 + k;
                float  wt = __ldg(wp + t);
                float4 r  = __ldg(rp + (size_t)t * (DD / 4));
                float4 m  = __ldg(ip + (size_t)t * (DD / 4));
                ar.x = fmaf(r.x, wt, ar.x);  ar.y = fmaf(r.y, wt, ar.y);
                ar.z = fmaf(r.z, wt, ar.z);  ar.w = fmaf(r.w, wt, ar.w);
                ai.x = fmaf(m.x, wt, ai.x);  ai.y = fmaf(m.y, wt, ai.y);
                ai.z = fmaf(m.z, wt, ai.z);  ai.w = fmaf(m.w, wt, ai.w);
            }
            sr[tg][j] = ar;
            si[tg][j] = ai;
            __syncthreads();

            if (tid < 64) {
                int q = tid >> 5;     // 0 = real, 1 = imag
                int l = tid & 31;
                float4 acc = make_float4(0.f, 0.f, 0.f, 0.f);
#pragma unroll
                for (int k = 0; k < 8; ++k) {
                    float4 v = q ? si[k][l] : sr[k][l];
                    acc.x += v.x; acc.y += v.y; acc.z += v.z; acc.w += v.w;
                }
                float4* dst = (float4*)(q ? g_outi : g_outr);
                dst[((size_t)b * DD + chunk * 128 + l * 4) >> 2] = acc;
            }
            __threadfence();          // publish data before flag
            __syncthreads();          // all stores (incl. combine) done + smem safe to reuse
            if (tid == 0) atomicAdd(&g_ready[b], 1);
        }

    } else {
        // ───────────── outer: 32 blocks per batch ─────────────
        float4* sr4 = (float4*)(smem_raw);          // out_r[b,:]
        float4* si4 = (float4*)(smem_raw + 2048);   // out_i[b,:]

        int obid = bid - NRED;
        int b    = obid >> 5;
        int tile = obid & 31;

        if (tid == 0) {
            // wait for this batch's 4 producer arrivals
            int ns = 32;
            while (atomicAdd(&g_ready[b], 0) < 4) {
                __nanosleep(ns);
                if (ns < 1024) ns <<= 1;
            }
            // consumed-count; 32nd consumer resets flags for the next replay
            // (safe: all 32 consumers have passed their wait by then)
            if (atomicAdd(&g_done[b], 1) == 31) {
                atomicExch(&g_ready[b], 0);
                atomicExch(&g_done[b], 0);
            }
        }
        __syncthreads();
        __threadfence();   // acquire ordering for g_out reads

        const float4* gr = (const float4*)(g_outr + b * DD);
        const float4* gi = (const float4*)(g_outi + b * DD);
        if (tid < 128) sr4[tid] = gr[tid];
        else           si4[tid - 128] = gi[tid - 128];
        __syncthreads();

        const float* srf = (const float*)sr4;
        const float* sif = (const float*)si4;

        int j4 = tid & 127;
        int ih = tid >> 7;

        float4 br = sr4[j4];
        float4 bi = si4[j4];

        float4* outr = (float4*)(out + (size_t)b * DD * DD)
                       + (size_t)(tile * 16) * 128 + j4;
        float4* outi = outr + (size_t)BB * DD * DD / 4;

#pragma unroll
        for (int k = 0; k < 8; ++k) {
            int row = k * 2 + ih;
            int i   = tile * 16 + row;
            float arw = srf[i];
            float aiw = sif[i];
            float4 vr, vi;
            vr.x = fmaf(arw, br.x, aiw * bi.x);
            vr.y = fmaf(arw, br.y, aiw * bi.y);
            vr.z = fmaf(arw, br.z, aiw * bi.z);
            vr.w = fmaf(arw, br.w, aiw * bi.w);
            vi.x = fmaf(aiw, br.x, -arw * bi.x);
            vi.y = fmaf(aiw, br.y, -arw * bi.y);
            vi.z = fmaf(aiw, br.z, -arw * bi.z);
            vi.w = fmaf(aiw, br.w, -arw * bi.w);
            __stcs(&outr[(size_t)row * 128], vr);   // streaming stores
            __stcs(&outi[(size_t)row * 128], vi);
        }
    }
}

extern "C" void kernel_launch(void* const* d_in, const int* in_sizes, int n_in,
                              void* d_out, int out_size) {
    const float* re = (const float*)d_in[0];   // input_real [128,128,512]
    const float* im = (const float*)d_in[1];   // input_imag [128,128,512]
    const float* w  = (const float*)d_in[2];   // weight     [128,128]
    float* out = (float*)d_out;                // [2,128,512,512]

    main_k<<<NRED + NOUT, 256>>>(re, im, w, out);
}

// round 11
// speedup vs baseline: 1.3263x; 1.3263x over previous
#include <cuda_runtime.h>

// ComplexSuperposition: B=128, T=128, D=512
// Two-kernel structure (proven fastest) with:
//   reduce_k: 1024 CTAs, 16-way T-split, weights preloaded in registers,
//             16 fully-unrolled LDG.128 per thread. Ends with PDL trigger.
//   outer_k : unchanged write-roofline streamer, launched with
//             ProgrammaticStreamSerialization; waits via
//             cudaGridDependencySynchronize() so its launch/ramp overlaps
//             the reduce tail.
// d_out: [output_r (128*512*512 f32)][output_i (...)]

#define BB 128
#define TT 128
#define DD 512

__device__ float g_outr[BB * DD];
__device__ float g_outi[BB * DD];

// grid = B * 8 = 1024 blocks, 256 threads.
// block: (b, c64) where c64 = 64-float chunk of D (16 float4).
// thread: j = tid & 15 (float4 lane), tg = tid >> 4 (T-group, 8 t's each).
__global__ void __launch_bounds__(256) reduce_k(const float* __restrict__ re,
                                                const float* __restrict__ im,
                                                const float* __restrict__ w) {
    __shared__ float4 sr[16][16];   // 4 KB
    __shared__ float4 si[16][16];   // 4 KB

    int b   = blockIdx.x >> 3;
    int c64 = blockIdx.x & 7;
    int tid = threadIdx.x;
    int j   = tid & 15;
    int tg  = tid >> 4;

    // preload this group's 8 weights into registers (off the critical loop)
    float wreg[8];
#pragma unroll
    for (int k = 0; k < 8; ++k)
        wreg[k] = __ldg(w + b * TT + tg * 8 + k);

    size_t base4 = (size_t)b * TT * (DD / 4) + c64 * 16 + j;
    const float4* rp = (const float4*)re + base4;
    const float4* ip = (const float4*)im + base4;

    float4 ar = make_float4(0.f, 0.f, 0.f, 0.f);
    float4 ai = make_float4(0.f, 0.f, 0.f, 0.f);

    int t0 = tg * 8;
#pragma unroll
    for (int k = 0; k < 8; ++k) {
        int t = t0 + k;
        float4 r = __ldg(rp + (size_t)t * (DD / 4));
        float4 m = __ldg(ip + (size_t)t * (DD / 4));
        float wt = wreg[k];
        ar.x = fmaf(r.x, wt, ar.x);  ar.y = fmaf(r.y, wt, ar.y);
        ar.z = fmaf(r.z, wt, ar.z);  ar.w = fmaf(r.w, wt, ar.w);
        ai.x = fmaf(m.x, wt, ai.x);  ai.y = fmaf(m.y, wt, ai.y);
        ai.z = fmaf(m.z, wt, ai.z);  ai.w = fmaf(m.w, wt, ai.w);
    }
    sr[tg][j] = ar;
    si[tg][j] = ai;
    __syncthreads();

    if (tid < 32) {
        int q = tid >> 4;          // 0 = real, 1 = imag
        int l = tid & 15;
        float4 acc = make_float4(0.f, 0.f, 0.f, 0.f);
#pragma unroll
        for (int g = 0; g < 16; ++g) {
            float4 v = q ? si[g][l] : sr[g][l];
            acc.x += v.x; acc.y += v.y; acc.z += v.z; acc.w += v.w;
        }
        float4* dst = (float4*)(q ? g_outi : g_outr);
        dst[(size_t)b * (DD / 4) + c64 * 16 + l] = acc;
        __threadfence();           // publish before PDL trigger
    }
    __syncthreads();
#if __CUDA_ARCH__ >= 900
    cudaTriggerProgrammaticLaunchCompletion();
#endif
}

// One block = one batch b, one 16-row tile of i. 32 tiles per batch.
__global__ void __launch_bounds__(256) outer_k(float* __restrict__ out) {
    __shared__ float4 sr4[DD / 4];
    __shared__ float4 si4[DD / 4];

    int b    = blockIdx.x >> 5;
    int tile = blockIdx.x & 31;
    int tid  = threadIdx.x;

    // address setup before the dependency sync (free overlap work)
    int j4 = tid & 127;
    int ih = tid >> 7;
    float4* outr = (float4*)(out + (size_t)b * DD * DD)
                   + (size_t)(tile * 16) * 128 + j4;
    float4* outi = outr + (size_t)BB * DD * DD / 4;

#if __CUDA_ARCH__ >= 900
    cudaGridDependencySynchronize();   // wait for reduce_k results
#endif

    const float4* gr = (const float4*)(g_outr + b * DD);
    const float4* gi = (const float4*)(g_outi + b * DD);
    if (tid < 128) sr4[tid] = gr[tid];
    else           si4[tid - 128] = gi[tid - 128];
    __syncthreads();

    const float* srf = (const float*)sr4;
    const float* sif = (const float*)si4;

    float4 br = sr4[j4];
    float4 bi = si4[j4];

#pragma unroll
    for (int k = 0; k < 8; ++k) {
        int row = k * 2 + ih;
        int i   = tile * 16 + row;
        float arw = srf[i];
        float aiw = sif[i];
        float4 vr, vi;
        vr.x = fmaf(arw, br.x, aiw * bi.x);
        vr.y = fmaf(arw, br.y, aiw * bi.y);
        vr.z = fmaf(arw, br.z, aiw * bi.z);
        vr.w = fmaf(arw, br.w, aiw * bi.w);
        vi.x = fmaf(aiw, br.x, -arw * bi.x);
        vi.y = fmaf(aiw, br.y, -arw * bi.y);
        vi.z = fmaf(aiw, br.z, -arw * bi.z);
        vi.w = fmaf(aiw, br.w, -arw * bi.w);
        __stcs(&outr[(size_t)row * 128], vr);   // streaming: never re-read
        __stcs(&outi[(size_t)row * 128], vi);
    }
}

extern "C" void kernel_launch(void* const* d_in, const int* in_sizes, int n_in,
                              void* d_out, int out_size) {
    const float* re = (const float*)d_in[0];   // input_real [128,128,512]
    const float* im = (const float*)d_in[1];   // input_imag [128,128,512]
    const float* w  = (const float*)d_in[2];   // weight     [128,128]
    float* out = (float*)d_out;                // [2,128,512,512]

    reduce_k<<<BB * 8, 256>>>(re, im, w);

    // outer_k with Programmatic Dependent Launch: starts ramping while
    // reduce_k drains; correctness via cudaGridDependencySynchronize().
    cudaLaunchConfig_t cfg = {};
    cfg.gridDim  = dim3(BB * 32);
    cfg.blockDim = dim3(256);
    cfg.dynamicSmemBytes = 0;
    cfg.stream = 0;
    cudaLaunchAttribute attr[1];
    attr[0].id = cudaLaunchAttributeProgrammaticStreamSerialization;
    attr[0].val.programmaticStreamSerializationAllowed = 1;
    cfg.attrs = attr;
    cfg.numAttrs = 1;
    cudaLaunchKernelEx(&cfg, outer_k, (float*)d_out);
}